// round 12
// baseline (speedup 1.0000x reference)
#include <cuda_runtime.h>
#include <cuda_fp16.h>

#define NB 8
#define NT 256   // TE == TD
#define ND 256
#define NU 256

// Scratch (no allocations allowed in kernel_launch)
__device__ float g_ae[NB*NT*NU];      // (B*TE, U)
__device__ float g_ad[NB*NT*NU];      // (B*TD, U)
__device__ float g_alphas[NB*NT*NT];  // (B, TD, TE)
__device__ float g_maxmu[NB*NT];      // (B, TD)
__device__ float g_hhat[NB*ND];       // (B, D)

__device__ __forceinline__ __half2 tanh_h2(__half2 h){
    unsigned u = *reinterpret_cast<unsigned*>(&h);
    unsigned r;
    asm("tanh.approx.f16x2 %0, %1;" : "=r"(r) : "r"(u));
    return *reinterpret_cast<__half2*>(&r);
}

__device__ __forceinline__ void cp_async16(void* smem_dst, const void* gsrc){
    unsigned sa = (unsigned)__cvta_generic_to_shared(smem_dst);
    asm volatile("cp.async.cg.shared.global [%0], [%1], 16;\n" :: "r"(sa), "l"(gsrc));
}
__device__ __forceinline__ void cp_async_commit(){ asm volatile("cp.async.commit_group;\n" ::: "memory"); }
__device__ __forceinline__ void cp_async_wait0(){ asm volatile("cp.async.wait_group 0;\n" ::: "memory"); }

// ---------------------------------------------------------------------------
// K1 v5 (unchanged): ae = en @ w_en, ad = de @ w_de.
// grid 128, 512 threads, 8 big stages via cp.async. ~fp32 FMA floor.
// ---------------------------------------------------------------------------
__global__ void __launch_bounds__(512) k1_proj(
    const float* __restrict__ en, const float* __restrict__ de,
    const float* __restrict__ w_en, const float* __restrict__ w_de)
{
    extern __shared__ float smem[];
    float*  s_in = smem;                       // 32 rows x 256 = 8192 floats (32KB)
    float4* s_w  = (float4*)(smem + 32*ND);    // [2][32*64] float4 (2x32KB)

    int bb = blockIdx.x;
    bool isA = bb < 64;
    int rb = (isA ? bb : bb - 64) * 32;            // row base in [0,2048)
    const float* in = isA ? en : de;
    const float* w  = isA ? w_en : w_de;
    float* out      = isA ? g_ae : g_ad;
    int tid = threadIdx.x;

    {
        const float4* in4 = (const float4*)(in + rb*ND);
        const float4* w4  = (const float4*)w;
        #pragma unroll
        for (int i = 0; i < 4; i++)
            cp_async16(&((float4*)s_in)[tid + i*512], &in4[tid + i*512]);
        #pragma unroll
        for (int i = 0; i < 4; i++)
            cp_async16(&s_w[tid + i*512], &w4[tid + i*512]);
        cp_async_commit();
        cp_async_wait0();
    }
    __syncthreads();

    const float4* w4 = (const float4*)w;     // flat [d*64 + ug]
    int tx = tid & 63;        // u-group of 4
    int ty = tid >> 6;        // 0..7 -> rows ty*4..ty*4+3 (warp-uniform)
    const float* srow = s_in + ty*4*ND;

    float4 a0 = make_float4(0.f,0.f,0.f,0.f);
    float4 a1 = a0, a2 = a0, a3 = a0;

    for (int st = 0; st < 8; st++){
        int cur = st & 1;
        if (st < 7){
            float4* dst = s_w + (cur^1)*2048;
            const float4* src = w4 + (st+1)*2048;
            #pragma unroll
            for (int i = 0; i < 4; i++)
                cp_async16(&dst[tid + i*512], &src[tid + i*512]);
            cp_async_commit();
        }
        const float4* wst = s_w + cur*2048;
        #pragma unroll 2
        for (int dg = 0; dg < 8; dg++){          // 8 groups of 4 d
            int dbase = st*32 + dg*4;
            float4 x0 = *(const float4*)&srow[0*ND + dbase];
            float4 x1 = *(const float4*)&srow[1*ND + dbase];
            float4 x2 = *(const float4*)&srow[2*ND + dbase];
            float4 x3 = *(const float4*)&srow[3*ND + dbase];
            #pragma unroll
            for (int jj = 0; jj < 4; jj++){
                float4 wv = wst[(dg*4 + jj)*64 + tx];
                float xs0 = (&x0.x)[jj];
                float xs1 = (&x1.x)[jj];
                float xs2 = (&x2.x)[jj];
                float xs3 = (&x3.x)[jj];
                a0.x = fmaf(xs0, wv.x, a0.x); a0.y = fmaf(xs0, wv.y, a0.y);
                a0.z = fmaf(xs0, wv.z, a0.z); a0.w = fmaf(xs0, wv.w, a0.w);
                a1.x = fmaf(xs1, wv.x, a1.x); a1.y = fmaf(xs1, wv.y, a1.y);
                a1.z = fmaf(xs1, wv.z, a1.z); a1.w = fmaf(xs1, wv.w, a1.w);
                a2.x = fmaf(xs2, wv.x, a2.x); a2.y = fmaf(xs2, wv.y, a2.y);
                a2.z = fmaf(xs2, wv.z, a2.z); a2.w = fmaf(xs2, wv.w, a2.w);
                a3.x = fmaf(xs3, wv.x, a3.x); a3.y = fmaf(xs3, wv.y, a3.y);
                a3.z = fmaf(xs3, wv.z, a3.z); a3.w = fmaf(xs3, wv.w, a3.w);
            }
        }
        if (st < 7) cp_async_wait0();
        __syncthreads();
    }

    int r = rb + ty*4;
    ((float4*)(out + (r+0)*NU))[tx] = a0;
    ((float4*)(out + (r+1)*NU))[tx] = a1;
    ((float4*)(out + (r+2)*NU))[tx] = a2;
    ((float4*)(out + (r+3)*NU))[tx] = a3;
}

// ---------------------------------------------------------------------------
// K2 v3: mu via tanh.approx.f16x2 — one MUFU op per TWO tanh.
// Per k-pair per s-row: 2 FADD (fp32 args) -> pack f16x2 -> tanh2 -> unpack
// -> 2 fp32 FMA with nu. MUFU load halves; fma/alu pipes absorb the rest.
// Accumulation stays fp32. Softmax unchanged (fp32).
// ---------------------------------------------------------------------------
__global__ void __launch_bounds__(256) k2_mu(const float* __restrict__ nu)
{
    __shared__ float s_mu[4][256];
    int blk  = blockIdx.x;
    int b    = blk >> 6;              // 64 blocks per batch
    int s0   = (blk & 63) * 4;
    int lane = threadIdx.x & 31;
    int w    = threadIdx.x >> 5;

    float nur[8], adr0[8], adr1[8], adr2[8], adr3[8];
    #pragma unroll
    for (int k = 0; k < 8; k++) nur[k] = nu[lane + 32*k];
    const float* adb = g_ad + (b*NT + s0)*NU;
    #pragma unroll
    for (int k = 0; k < 8; k++){
        int u = lane + 32*k;
        adr0[k] = adb[0*NU + u];
        adr1[k] = adb[1*NU + u];
        adr2[k] = adb[2*NU + u];
        adr3[k] = adb[3*NU + u];
    }
    const float* aeb = g_ae + b*NT*NU;

    for (int ti = 0; ti < 32; ti++){
        int t = ti*8 + w;
        const float* aet = aeb + t*NU;
        float a0=0.f, a1=0.f, a2=0.f, a3=0.f;
        #pragma unroll
        for (int kp = 0; kp < 4; kp++){
            int ka = 2*kp, kb = 2*kp + 1;
            float ea = aet[lane + 32*ka];
            float eb = aet[lane + 32*kb];
            float2 f;
            f = __half22float2(tanh_h2(__floats2half2_rn(adr0[ka] + ea, adr0[kb] + eb)));
            a0 = fmaf(f.x, nur[ka], a0); a0 = fmaf(f.y, nur[kb], a0);
            f = __half22float2(tanh_h2(__floats2half2_rn(adr1[ka] + ea, adr1[kb] + eb)));
            a1 = fmaf(f.x, nur[ka], a1); a1 = fmaf(f.y, nur[kb], a1);
            f = __half22float2(tanh_h2(__floats2half2_rn(adr2[ka] + ea, adr2[kb] + eb)));
            a2 = fmaf(f.x, nur[ka], a2); a2 = fmaf(f.y, nur[kb], a2);
            f = __half22float2(tanh_h2(__floats2half2_rn(adr3[ka] + ea, adr3[kb] + eb)));
            a3 = fmaf(f.x, nur[ka], a3); a3 = fmaf(f.y, nur[kb], a3);
        }
        #pragma unroll
        for (int off = 16; off; off >>= 1){
            a0 += __shfl_xor_sync(0xffffffffu, a0, off);
            a1 += __shfl_xor_sync(0xffffffffu, a1, off);
            a2 += __shfl_xor_sync(0xffffffffu, a2, off);
            a3 += __shfl_xor_sync(0xffffffffu, a3, off);
        }
        if (lane == 0){
            s_mu[0][t] = a0; s_mu[1][t] = a1;
            s_mu[2][t] = a2; s_mu[3][t] = a3;
        }
    }
    __syncthreads();

    if (w < 4){
        int s = w;
        float v[8];
        float m = -1e30f;
        #pragma unroll
        for (int j = 0; j < 8; j++){ v[j] = s_mu[s][lane + 32*j]; m = fmaxf(m, v[j]); }
        #pragma unroll
        for (int off = 16; off; off >>= 1) m = fmaxf(m, __shfl_xor_sync(0xffffffffu, m, off));
        float sum = 0.f;
        #pragma unroll
        for (int j = 0; j < 8; j++){ v[j] = __expf(v[j] - m); sum += v[j]; }
        #pragma unroll
        for (int off = 16; off; off >>= 1) sum += __shfl_xor_sync(0xffffffffu, sum, off);
        float inv = 1.0f / sum;
        float* arow = g_alphas + (b*NT + s0 + s)*NT;
        #pragma unroll
        for (int j = 0; j < 8; j++) arow[lane + 32*j] = v[j] * inv;
        if (lane == 0) g_maxmu[b*NT + s0 + s] = m;
    }
}

// ---------------------------------------------------------------------------
// K3 (unchanged, ~3us)
// ---------------------------------------------------------------------------
__global__ void __launch_bounds__(256) k3_hhat(const float* __restrict__ de)
{
    __shared__ float s_ma[256];
    __shared__ float s_red[8];
    int b = blockIdx.x;
    int tid = threadIdx.x, lane = tid & 31, w = tid >> 5;

    float v = g_maxmu[b*NT + tid];
    float m = v;
    #pragma unroll
    for (int off = 16; off; off >>= 1) m = fmaxf(m, __shfl_xor_sync(0xffffffffu, m, off));
    if (lane == 0) s_red[w] = m;
    __syncthreads();
    m = s_red[0];
    #pragma unroll
    for (int i = 1; i < 8; i++) m = fmaxf(m, s_red[i]);
    __syncthreads();

    float e = __expf(v - m);
    float psum = e;
    #pragma unroll
    for (int off = 16; off; off >>= 1) psum += __shfl_xor_sync(0xffffffffu, psum, off);
    if (lane == 0) s_red[w] = psum;
    __syncthreads();
    float tot = 0.f;
    #pragma unroll
    for (int i = 0; i < 8; i++) tot += s_red[i];
    s_ma[tid] = e / tot;
    __syncthreads();

    int d = tid;
    const float* deb = de + b*NT*ND;
    float acc = 0.f;
    #pragma unroll 4
    for (int s = 0; s < NT; s++) acc = fmaf(deb[s*ND + d], s_ma[s], acc);
    g_hhat[b*ND + d] = acc;
}

// ---------------------------------------------------------------------------
// K4 v6 (unchanged, 14.7us — near fp32 FMA floor for this tiling)
// ---------------------------------------------------------------------------
__global__ void __launch_bounds__(256) k4_out(
    const float* __restrict__ en, const float* __restrict__ de,
    float* __restrict__ out)
{
    extern __shared__ float smem[];
    float*  s_at = smem;                        // [t][s pad 20]: 256*20 floats (20KB)
    float4* s_en = (float4*)(smem + NT*20);     // [2][64*64] float4 (2x64KB)

    int blk = blockIdx.x;
    int b   = blk >> 4;
    int s0  = (blk & 15) * 16;
    int tid = threadIdx.x;

    {
        const float* ab = g_alphas + (b*NT + s0)*NT;
        #pragma unroll
        for (int i = 0; i < 16; i++){
            int flat = tid + i*256;
            int s = flat >> 8;               // 0..15
            int t = flat & 255;
            s_at[t*20 + s] = ab[s*NT + t];
        }
    }

    const float4* en4 = (const float4*)(en + b*NT*ND);   // 16384 float4

    #pragma unroll
    for (int i = 0; i < 16; i++)
        cp_async16(&s_en[tid + i*256], &en4[tid + i*256]);
    cp_async_commit();
    cp_async_wait0();
    __syncthreads();

    int tx = tid & 63;        // d-group of 4
    int ty = tid >> 6;        // 0..3 -> s rows ty*4..ty*4+3 (warp-uniform)

    float4 c0 = make_float4(0.f,0.f,0.f,0.f);
    float4 c1 = c0, c2 = c0, c3 = c0;

    for (int st = 0; st < 4; st++){
        int cur = st & 1;
        if (st < 3){
            float4* dst = s_en + (cur^1)*4096;
            const float4* src = en4 + (st+1)*4096;
            #pragma unroll
            for (int i = 0; i < 16; i++)
                cp_async16(&dst[tid + i*256], &src[tid + i*256]);
            cp_async_commit();
        }
        const float4* est = s_en + cur*4096;
        #pragma unroll 4
        for (int j = 0; j < 64; j++){
            int t = st*64 + j;
            float4 e  = est[j*64 + tx];
            float4 xa = *(const float4*)&s_at[t*20 + ty*4];
            c0.x = fmaf(xa.x, e.x, c0.x); c0.y = fmaf(xa.x, e.y, c0.y);
            c0.z = fmaf(xa.x, e.z, c0.z); c0.w = fmaf(xa.x, e.w, c0.w);
            c1.x = fmaf(xa.y, e.x, c1.x); c1.y = fmaf(xa.y, e.y, c1.y);
            c1.z = fmaf(xa.y, e.z, c1.z); c1.w = fmaf(xa.y, e.w, c1.w);
            c2.x = fmaf(xa.z, e.x, c2.x); c2.y = fmaf(xa.z, e.y, c2.y);
            c2.z = fmaf(xa.z, e.z, c2.z); c2.w = fmaf(xa.z, e.w, c2.w);
            c3.x = fmaf(xa.w, e.x, c3.x); c3.y = fmaf(xa.w, e.y, c3.y);
            c3.z = fmaf(xa.w, e.z, c3.z); c3.w = fmaf(xa.w, e.w, c3.w);
        }
        if (st < 3) cp_async_wait0();
        __syncthreads();
    }

    float4 hh = ((const float4*)(g_hhat + b*ND))[tx];
    float4 cs_arr[4] = {c0, c1, c2, c3};

    #pragma unroll
    for (int j = 0; j < 4; j++){
        int row = b*NT + s0 + ty*4 + j;
        float4 dv = ((const float4*)(de + row*ND))[tx];
        float4 cs = cs_arr[j];
        float4* o = (float4*)(out + (size_t)row * (4*ND));
        o[0*64 + tx] = dv;
        o[1*64 + tx] = cs;
        o[2*64 + tx] = make_float4(dv.x*cs.x, dv.y*cs.y, dv.z*cs.z, dv.w*cs.w);
        o[3*64 + tx] = make_float4(dv.x*hh.x, dv.y*hh.y, dv.z*hh.z, dv.w*hh.w);
    }
}

extern "C" void kernel_launch(void* const* d_in, const int* in_sizes, int n_in,
                              void* d_out, int out_size)
{
    const float* en   = (const float*)d_in[0];
    const float* de   = (const float*)d_in[1];
    const float* w_en = (const float*)d_in[2];
    const float* w_de = (const float*)d_in[3];
    const float* nu   = (const float*)d_in[4];
    float* out = (float*)d_out;

    const int K1_SMEM = 32*ND*4 + 2*32*64*16;           // 32KB + 64KB = 98304B
    const int K4_SMEM = NT*20*4 + 2*64*64*16;           // 20KB + 128KB = 151552B
    cudaFuncSetAttribute(k1_proj, cudaFuncAttributeMaxDynamicSharedMemorySize, K1_SMEM);
    cudaFuncSetAttribute(k4_out,  cudaFuncAttributeMaxDynamicSharedMemorySize, K4_SMEM);

    k1_proj<<<128, 512, K1_SMEM>>>(en, de, w_en, w_de);
    k2_mu  <<<512, 256>>>(nu);
    k3_hhat<<<NB,  256>>>(de);
    k4_out <<<128, 256, K4_SMEM>>>(en, de, out);
}

// round 13
// speedup vs baseline: 1.0266x; 1.0266x over previous
#include <cuda_runtime.h>
#include <cuda_fp16.h>

#define NB 8
#define NT 256   // TE == TD
#define ND 256
#define NU 256

// Scratch (no allocations allowed in kernel_launch)
__device__ __half g_ae_h[NB*NT*NU];   // (B*TE, U) in f16
__device__ __half g_ad_h[NB*NT*NU];   // (B*TD, U) in f16
__device__ float g_alphas[NB*NT*NT];  // (B, TD, TE)
__device__ float g_maxmu[NB*NT];      // (B, TD)
__device__ float g_hhat[NB*ND];       // (B, D)

__device__ __forceinline__ __half2 tanh_h2(__half2 h){
    unsigned u = *reinterpret_cast<unsigned*>(&h);
    unsigned r;
    asm("tanh.approx.f16x2 %0, %1;" : "=r"(r) : "r"(u));
    return *reinterpret_cast<__half2*>(&r);
}

__device__ __forceinline__ void cp_async16(void* smem_dst, const void* gsrc){
    unsigned sa = (unsigned)__cvta_generic_to_shared(smem_dst);
    asm volatile("cp.async.cg.shared.global [%0], [%1], 16;\n" :: "r"(sa), "l"(gsrc));
}
__device__ __forceinline__ void cp_async_commit(){ asm volatile("cp.async.commit_group;\n" ::: "memory"); }
__device__ __forceinline__ void cp_async_wait0(){ asm volatile("cp.async.wait_group 0;\n" ::: "memory"); }

// ---------------------------------------------------------------------------
// K1 v6: ae = en @ w_en, ad = de @ w_de — OUTPUT IN F16.
// grid 128, 512 threads, 8 big stages via cp.async. Compute stays f32;
// epilogue packs 4 consecutive u into 2 half2 (one uint2 store per row).
// ---------------------------------------------------------------------------
__global__ void __launch_bounds__(512) k1_proj(
    const float* __restrict__ en, const float* __restrict__ de,
    const float* __restrict__ w_en, const float* __restrict__ w_de)
{
    extern __shared__ float smem[];
    float*  s_in = smem;                       // 32 rows x 256 = 8192 floats (32KB)
    float4* s_w  = (float4*)(smem + 32*ND);    // [2][32*64] float4 (2x32KB)

    int bb = blockIdx.x;
    bool isA = bb < 64;
    int rb = (isA ? bb : bb - 64) * 32;            // row base in [0,2048)
    const float* in = isA ? en : de;
    const float* w  = isA ? w_en : w_de;
    __half* outh    = isA ? g_ae_h : g_ad_h;
    int tid = threadIdx.x;

    {
        const float4* in4 = (const float4*)(in + rb*ND);
        const float4* w4  = (const float4*)w;
        #pragma unroll
        for (int i = 0; i < 4; i++)
            cp_async16(&((float4*)s_in)[tid + i*512], &in4[tid + i*512]);
        #pragma unroll
        for (int i = 0; i < 4; i++)
            cp_async16(&s_w[tid + i*512], &w4[tid + i*512]);
        cp_async_commit();
        cp_async_wait0();
    }
    __syncthreads();

    const float4* w4 = (const float4*)w;     // flat [d*64 + ug]
    int tx = tid & 63;        // u-group of 4
    int ty = tid >> 6;        // 0..7 -> rows ty*4..ty*4+3 (warp-uniform)
    const float* srow = s_in + ty*4*ND;

    float4 a0 = make_float4(0.f,0.f,0.f,0.f);
    float4 a1 = a0, a2 = a0, a3 = a0;

    for (int st = 0; st < 8; st++){
        int cur = st & 1;
        if (st < 7){
            float4* dst = s_w + (cur^1)*2048;
            const float4* src = w4 + (st+1)*2048;
            #pragma unroll
            for (int i = 0; i < 4; i++)
                cp_async16(&dst[tid + i*512], &src[tid + i*512]);
            cp_async_commit();
        }
        const float4* wst = s_w + cur*2048;
        #pragma unroll 2
        for (int dg = 0; dg < 8; dg++){          // 8 groups of 4 d
            int dbase = st*32 + dg*4;
            float4 x0 = *(const float4*)&srow[0*ND + dbase];
            float4 x1 = *(const float4*)&srow[1*ND + dbase];
            float4 x2 = *(const float4*)&srow[2*ND + dbase];
            float4 x3 = *(const float4*)&srow[3*ND + dbase];
            #pragma unroll
            for (int jj = 0; jj < 4; jj++){
                float4 wv = wst[(dg*4 + jj)*64 + tx];
                float xs0 = (&x0.x)[jj];
                float xs1 = (&x1.x)[jj];
                float xs2 = (&x2.x)[jj];
                float xs3 = (&x3.x)[jj];
                a0.x = fmaf(xs0, wv.x, a0.x); a0.y = fmaf(xs0, wv.y, a0.y);
                a0.z = fmaf(xs0, wv.z, a0.z); a0.w = fmaf(xs0, wv.w, a0.w);
                a1.x = fmaf(xs1, wv.x, a1.x); a1.y = fmaf(xs1, wv.y, a1.y);
                a1.z = fmaf(xs1, wv.z, a1.z); a1.w = fmaf(xs1, wv.w, a1.w);
                a2.x = fmaf(xs2, wv.x, a2.x); a2.y = fmaf(xs2, wv.y, a2.y);
                a2.z = fmaf(xs2, wv.z, a2.z); a2.w = fmaf(xs2, wv.w, a2.w);
                a3.x = fmaf(xs3, wv.x, a3.x); a3.y = fmaf(xs3, wv.y, a3.y);
                a3.z = fmaf(xs3, wv.z, a3.z); a3.w = fmaf(xs3, wv.w, a3.w);
            }
        }
        if (st < 7) cp_async_wait0();
        __syncthreads();
    }

    int r = rb + ty*4;
    #pragma unroll
    for (int j = 0; j < 4; j++){
        float4 a = (j==0) ? a0 : (j==1) ? a1 : (j==2) ? a2 : a3;
        __half2 h01 = __floats2half2_rn(a.x, a.y);
        __half2 h23 = __floats2half2_rn(a.z, a.w);
        uint2 p;
        p.x = *reinterpret_cast<unsigned*>(&h01);
        p.y = *reinterpret_cast<unsigned*>(&h23);
        ((uint2*)(outh + (r+j)*NU))[tx] = p;      // halves 4tx..4tx+3
    }
}

// ---------------------------------------------------------------------------
// K2 v4: mu entirely in f16x2: HADD2 -> tanh2 -> HFMA2 (half2 acc over the
// lane's 4 half2 = 8 u), flushed to f32 once per (s,t). MUFU-bound at
// ~4 cyc/elem -> ~20-22us. Lane owns u = 8*lane..8*lane+7 (one LDG.128/t).
// Softmax in f32 unchanged.
// ---------------------------------------------------------------------------
__global__ void __launch_bounds__(256) k2_mu(const float* __restrict__ nu)
{
    __shared__ float s_mu[4][256];
    int blk  = blockIdx.x;
    int b    = blk >> 6;              // 64 blocks per batch
    int s0   = (blk & 63) * 4;
    int lane = threadIdx.x & 31;
    int w    = threadIdx.x >> 5;

    // nu packed to half2: lane's u = 8*lane + {0..7}
    __half2 nu2[4];
    {
        const float4* nuf4 = (const float4*)nu;
        float4 n0 = nuf4[2*lane];
        float4 n1 = nuf4[2*lane + 1];
        nu2[0] = __floats2half2_rn(n0.x, n0.y);
        nu2[1] = __floats2half2_rn(n0.z, n0.w);
        nu2[2] = __floats2half2_rn(n1.x, n1.y);
        nu2[3] = __floats2half2_rn(n1.z, n1.w);
    }

    // ad rows (4 s) as half2 registers
    __half2 adh[4][4];
    {
        const uint4* adb = (const uint4*)(g_ad_h + (b*NT + s0)*NU);  // 32 uint4/row
        #pragma unroll
        for (int s = 0; s < 4; s++){
            uint4 v = adb[s*32 + lane];
            adh[s][0] = *reinterpret_cast<__half2*>(&v.x);
            adh[s][1] = *reinterpret_cast<__half2*>(&v.y);
            adh[s][2] = *reinterpret_cast<__half2*>(&v.z);
            adh[s][3] = *reinterpret_cast<__half2*>(&v.w);
        }
    }
    const uint4* aeb = (const uint4*)(g_ae_h + b*NT*NU);

    const __half2 zero2 = __float2half2_rn(0.f);

    for (int ti = 0; ti < 32; ti++){
        int t = ti*8 + w;
        uint4 ev = aeb[t*32 + lane];
        __half2 e2[4];
        e2[0] = *reinterpret_cast<__half2*>(&ev.x);
        e2[1] = *reinterpret_cast<__half2*>(&ev.y);
        e2[2] = *reinterpret_cast<__half2*>(&ev.z);
        e2[3] = *reinterpret_cast<__half2*>(&ev.w);

        float a0, a1, a2, a3;
        {
            __half2 acc = zero2;
            #pragma unroll
            for (int j = 0; j < 4; j++)
                acc = __hfma2(tanh_h2(__hadd2(adh[0][j], e2[j])), nu2[j], acc);
            float2 f = __half22float2(acc); a0 = f.x + f.y;
        }
        {
            __half2 acc = zero2;
            #pragma unroll
            for (int j = 0; j < 4; j++)
                acc = __hfma2(tanh_h2(__hadd2(adh[1][j], e2[j])), nu2[j], acc);
            float2 f = __half22float2(acc); a1 = f.x + f.y;
        }
        {
            __half2 acc = zero2;
            #pragma unroll
            for (int j = 0; j < 4; j++)
                acc = __hfma2(tanh_h2(__hadd2(adh[2][j], e2[j])), nu2[j], acc);
            float2 f = __half22float2(acc); a2 = f.x + f.y;
        }
        {
            __half2 acc = zero2;
            #pragma unroll
            for (int j = 0; j < 4; j++)
                acc = __hfma2(tanh_h2(__hadd2(adh[3][j], e2[j])), nu2[j], acc);
            float2 f = __half22float2(acc); a3 = f.x + f.y;
        }

        #pragma unroll
        for (int off = 16; off; off >>= 1){
            a0 += __shfl_xor_sync(0xffffffffu, a0, off);
            a1 += __shfl_xor_sync(0xffffffffu, a1, off);
            a2 += __shfl_xor_sync(0xffffffffu, a2, off);
            a3 += __shfl_xor_sync(0xffffffffu, a3, off);
        }
        if (lane == 0){
            s_mu[0][t] = a0; s_mu[1][t] = a1;
            s_mu[2][t] = a2; s_mu[3][t] = a3;
        }
    }
    __syncthreads();

    if (w < 4){
        int s = w;
        float v[8];
        float m = -1e30f;
        #pragma unroll
        for (int j = 0; j < 8; j++){ v[j] = s_mu[s][lane + 32*j]; m = fmaxf(m, v[j]); }
        #pragma unroll
        for (int off = 16; off; off >>= 1) m = fmaxf(m, __shfl_xor_sync(0xffffffffu, m, off));
        float sum = 0.f;
        #pragma unroll
        for (int j = 0; j < 8; j++){ v[j] = __expf(v[j] - m); sum += v[j]; }
        #pragma unroll
        for (int off = 16; off; off >>= 1) sum += __shfl_xor_sync(0xffffffffu, sum, off);
        float inv = 1.0f / sum;
        float* arow = g_alphas + (b*NT + s0 + s)*NT;
        #pragma unroll
        for (int j = 0; j < 8; j++) arow[lane + 32*j] = v[j] * inv;
        if (lane == 0) g_maxmu[b*NT + s0 + s] = m;
    }
}

// ---------------------------------------------------------------------------
// K3 (unchanged, ~3us)
// ---------------------------------------------------------------------------
__global__ void __launch_bounds__(256) k3_hhat(const float* __restrict__ de)
{
    __shared__ float s_ma[256];
    __shared__ float s_red[8];
    int b = blockIdx.x;
    int tid = threadIdx.x, lane = tid & 31, w = tid >> 5;

    float v = g_maxmu[b*NT + tid];
    float m = v;
    #pragma unroll
    for (int off = 16; off; off >>= 1) m = fmaxf(m, __shfl_xor_sync(0xffffffffu, m, off));
    if (lane == 0) s_red[w] = m;
    __syncthreads();
    m = s_red[0];
    #pragma unroll
    for (int i = 1; i < 8; i++) m = fmaxf(m, s_red[i]);
    __syncthreads();

    float e = __expf(v - m);
    float psum = e;
    #pragma unroll
    for (int off = 16; off; off >>= 1) psum += __shfl_xor_sync(0xffffffffu, psum, off);
    if (lane == 0) s_red[w] = psum;
    __syncthreads();
    float tot = 0.f;
    #pragma unroll
    for (int i = 0; i < 8; i++) tot += s_red[i];
    s_ma[tid] = e / tot;
    __syncthreads();

    int d = tid;
    const float* deb = de + b*NT*ND;
    float acc = 0.f;
    #pragma unroll 4
    for (int s = 0; s < NT; s++) acc = fmaf(deb[s*ND + d], s_ma[s], acc);
    g_hhat[b*ND + d] = acc;
}

// ---------------------------------------------------------------------------
// K4 v6 (unchanged, ~15us — near fp32 FMA floor for this tiling)
// ---------------------------------------------------------------------------
__global__ void __launch_bounds__(256) k4_out(
    const float* __restrict__ en, const float* __restrict__ de,
    float* __restrict__ out)
{
    extern __shared__ float smem[];
    float*  s_at = smem;                        // [t][s pad 20]: 256*20 floats (20KB)
    float4* s_en = (float4*)(smem + NT*20);     // [2][64*64] float4 (2x64KB)

    int blk = blockIdx.x;
    int b   = blk >> 4;
    int s0  = (blk & 15) * 16;
    int tid = threadIdx.x;

    {
        const float* ab = g_alphas + (b*NT + s0)*NT;
        #pragma unroll
        for (int i = 0; i < 16; i++){
            int flat = tid + i*256;
            int s = flat >> 8;               // 0..15
            int t = flat & 255;
            s_at[t*20 + s] = ab[s*NT + t];
        }
    }

    const float4* en4 = (const float4*)(en + b*NT*ND);   // 16384 float4

    #pragma unroll
    for (int i = 0; i < 16; i++)
        cp_async16(&s_en[tid + i*256], &en4[tid + i*256]);
    cp_async_commit();
    cp_async_wait0();
    __syncthreads();

    int tx = tid & 63;        // d-group of 4
    int ty = tid >> 6;        // 0..3 -> s rows ty*4..ty*4+3 (warp-uniform)

    float4 c0 = make_float4(0.f,0.f,0.f,0.f);
    float4 c1 = c0, c2 = c0, c3 = c0;

    for (int st = 0; st < 4; st++){
        int cur = st & 1;
        if (st < 3){
            float4* dst = s_en + (cur^1)*4096;
            const float4* src = en4 + (st+1)*4096;
            #pragma unroll
            for (int i = 0; i < 16; i++)
                cp_async16(&dst[tid + i*256], &src[tid + i*256]);
            cp_async_commit();
        }
        const float4* est = s_en + cur*4096;
        #pragma unroll 4
        for (int j = 0; j < 64; j++){
            int t = st*64 + j;
            float4 e  = est[j*64 + tx];
            float4 xa = *(const float4*)&s_at[t*20 + ty*4];
            c0.x = fmaf(xa.x, e.x, c0.x); c0.y = fmaf(xa.x, e.y, c0.y);
            c0.z = fmaf(xa.x, e.z, c0.z); c0.w = fmaf(xa.x, e.w, c0.w);
            c1.x = fmaf(xa.y, e.x, c1.x); c1.y = fmaf(xa.y, e.y, c1.y);
            c1.z = fmaf(xa.y, e.z, c1.z); c1.w = fmaf(xa.y, e.w, c1.w);
            c2.x = fmaf(xa.z, e.x, c2.x); c2.y = fmaf(xa.z, e.y, c2.y);
            c2.z = fmaf(xa.z, e.z, c2.z); c2.w = fmaf(xa.z, e.w, c2.w);
            c3.x = fmaf(xa.w, e.x, c3.x); c3.y = fmaf(xa.w, e.y, c3.y);
            c3.z = fmaf(xa.w, e.z, c3.z); c3.w = fmaf(xa.w, e.w, c3.w);
        }
        if (st < 3) cp_async_wait0();
        __syncthreads();
    }

    float4 hh = ((const float4*)(g_hhat + b*ND))[tx];
    float4 cs_arr[4] = {c0, c1, c2, c3};

    #pragma unroll
    for (int j = 0; j < 4; j++){
        int row = b*NT + s0 + ty*4 + j;
        float4 dv = ((const float4*)(de + row*ND))[tx];
        float4 cs = cs_arr[j];
        float4* o = (float4*)(out + (size_t)row * (4*ND));
        o[0*64 + tx] = dv;
        o[1*64 + tx] = cs;
        o[2*64 + tx] = make_float4(dv.x*cs.x, dv.y*cs.y, dv.z*cs.z, dv.w*cs.w);
        o[3*64 + tx] = make_float4(dv.x*hh.x, dv.y*hh.y, dv.z*hh.z, dv.w*hh.w);
    }
}

extern "C" void kernel_launch(void* const* d_in, const int* in_sizes, int n_in,
                              void* d_out, int out_size)
{
    const float* en   = (const float*)d_in[0];
    const float* de   = (const float*)d_in[1];
    const float* w_en = (const float*)d_in[2];
    const float* w_de = (const float*)d_in[3];
    const float* nu   = (const float*)d_in[4];
    float* out = (float*)d_out;

    const int K1_SMEM = 32*ND*4 + 2*32*64*16;           // 32KB + 64KB = 98304B
    const int K4_SMEM = NT*20*4 + 2*64*64*16;           // 20KB + 128KB = 151552B
    cudaFuncSetAttribute(k1_proj, cudaFuncAttributeMaxDynamicSharedMemorySize, K1_SMEM);
    cudaFuncSetAttribute(k4_out,  cudaFuncAttributeMaxDynamicSharedMemorySize, K4_SMEM);

    k1_proj<<<128, 512, K1_SMEM>>>(en, de, w_en, w_de);
    k2_mu  <<<512, 256>>>(nu);
    k3_hhat<<<NB,  256>>>(de);
    k4_out <<<128, 256, K4_SMEM>>>(en, de, out);
}